// round 4
// baseline (speedup 1.0000x reference)
#include <cuda_runtime.h>
#include <cuda_bf16.h>

#define B_      8
#define NVAL    1024
#define MVAL    1024
#define CIN     8
#define CREP    9
#define COUT    16

#define NSG     8                    // n-splits across blocks
#define NBLKN   (NVAL / NSG)         // 128 n per block
#define MBLK    64                   // m per block (2 per lane)
#define WARPS   8                    // warps per block (n-chunks within block)
#define NTHREADS (32 * WARPS)        // 256
#define NCHUNK  (NBLKN / WARPS)      // 16 n per warp

typedef unsigned long long u64;

// Partial sums: [NSG][B][M][CREP] = 2.36MB
__device__ float g_part[NSG * B_ * MVAL * CREP];

__device__ __forceinline__ u64 pack2(float lo, float hi) {
    u64 r; asm("mov.b64 %0, {%1, %2};" : "=l"(r) : "f"(lo), "f"(hi)); return r;
}
__device__ __forceinline__ void unpack2(u64 v, float& lo, float& hi) {
    asm("mov.b64 {%0, %1}, %2;" : "=f"(lo), "=f"(hi) : "l"(v));
}
__device__ __forceinline__ u64 add2(u64 a, u64 b) {
    u64 r; asm("add.rn.f32x2 %0, %1, %2;" : "=l"(r) : "l"(a), "l"(b)); return r;
}
__device__ __forceinline__ u64 mul2(u64 a, u64 b) {
    u64 r; asm("mul.rn.f32x2 %0, %1, %2;" : "=l"(r) : "l"(a), "l"(b)); return r;
}
__device__ __forceinline__ u64 fma2(u64 a, u64 b, u64 c) {
    u64 r; asm("fma.rn.f32x2 %0, %1, %2, %3;" : "=l"(r) : "l"(a), "l"(b), "l"(c)); return r;
}
__device__ __forceinline__ float ex2(float x) {   // MUFU.EX2
    float r; asm("ex2.approx.f32 %0, %1;" : "=f"(r) : "f"(x)); return r;
}

__global__ __launch_bounds__(NTHREADS)
void convcnp_partial(const float* __restrict__ gx,
                     const float* __restrict__ gy,
                     const float* __restrict__ gt,
                     const float* __restrict__ gsigma)
{
    __shared__ float s_x[NBLKN];
    __shared__ float s_xn[NBLKN];
    __shared__ float s_pool[WARPS * MBLK * CREP];   // 4608 floats; first 1024 double as s_y

    float* s_y = s_pool;

    const int nb  = blockIdx.x & (NSG - 1);
    const int mt  = (blockIdx.x >> 3) & 15;
    const int b   = blockIdx.x >> 7;
    const int tid = threadIdx.x;
    const int lane = tid & 31;
    const int ns   = tid >> 5;

    float kk[CREP];
    bool same = true;
    #pragma unroll
    for (int c = 0; c < CREP; c++) {
        float s = __expf(gsigma[c]);
        kk[c] = -0.5f * 1.4426950408889634f / (s * s);
        if (c > 0 && kk[c] != kk[0]) same = false;
    }
    const float sf = same ? sqrtf(-kk[0]) : 1.0f;

    const int nbase = nb * NBLKN;

    // Stage this block's n-slice of x (scaled +/-) and y
    for (int i = tid; i < NBLKN; i += NTHREADS) {
        float v = gx[b * NVAL + nbase + i] * sf;
        s_x [i] =  v;
        s_xn[i] = -v;
    }
    {
        const float4* y4 = (const float4*)(gy + (b * NVAL + nbase) * CIN);
        float4* sy4 = (float4*)s_y;
        sy4[tid] = y4[tid];                 // 256 threads x 16B = 4KB exactly
    }
    const int   m0  = mt * MBLK + lane;
    const int   m1  = m0 + 32;
    const float tmA = gt[b * MVAL + m0] * sf;
    const float tmB = gt[b * MVAL + m1] * sf;
    __syncthreads();

    const int n0 = ns * NCHUNK;
    float sumA[CREP], sumB[CREP];

    if (same) {
        const u64 ttA  = pack2( tmA,  tmA), nttA = pack2(-tmA, -tmA);
        const u64 ttB  = pack2( tmB,  tmB), nttB = pack2(-tmB, -tmB);
        u64 dA = 0, A12 = 0, A34 = 0, A56 = 0, A78 = 0;
        u64 dB = 0, B12 = 0, B34 = 0, B56 = 0, B78 = 0;

        #pragma unroll 4
        for (int n = n0; n < n0 + NCHUNK; n += 2) {
            u64 x2  = *(const u64*)&s_x [n];
            u64 xn2 = *(const u64*)&s_xn[n];
            ulonglong2 yA = *(const ulonglong2*)&s_y[n * CIN];
            ulonglong2 yB = *(const ulonglong2*)&s_y[n * CIN + 4];
            ulonglong2 zA = *(const ulonglong2*)&s_y[(n + 1) * CIN];
            ulonglong2 zB = *(const ulonglong2*)&s_y[(n + 1) * CIN + 4];

            u64 dd = mul2(add2(x2, nttA), add2(xn2, ttA));   // -(x-t)^2, pre-scaled
            float d0, d1; unpack2(dd, d0, d1);
            float e0 = ex2(d0), e1 = ex2(d1);
            dA = add2(dA, pack2(e0, e1));
            u64 e00 = pack2(e0, e0), e11 = pack2(e1, e1);
            A12 = fma2(e00, yA.x, A12);  A34 = fma2(e00, yA.y, A34);
            A56 = fma2(e00, yB.x, A56);  A78 = fma2(e00, yB.y, A78);
            A12 = fma2(e11, zA.x, A12);  A34 = fma2(e11, zA.y, A34);
            A56 = fma2(e11, zB.x, A56);  A78 = fma2(e11, zB.y, A78);

            u64 gg = mul2(add2(x2, nttB), add2(xn2, ttB));
            float g0, g1; unpack2(gg, g0, g1);
            float f0 = ex2(g0), f1 = ex2(g1);
            dB = add2(dB, pack2(f0, f1));
            u64 f00 = pack2(f0, f0), f11 = pack2(f1, f1);
            B12 = fma2(f00, yA.x, B12);  B34 = fma2(f00, yA.y, B34);
            B56 = fma2(f00, yB.x, B56);  B78 = fma2(f00, yB.y, B78);
            B12 = fma2(f11, zA.x, B12);  B34 = fma2(f11, zA.y, B34);
            B56 = fma2(f11, zB.x, B56);  B78 = fma2(f11, zB.y, B78);
        }
        float lo, hi;
        unpack2(dA, lo, hi);  sumA[0] = lo + hi;
        unpack2(A12, sumA[1], sumA[2]); unpack2(A34, sumA[3], sumA[4]);
        unpack2(A56, sumA[5], sumA[6]); unpack2(A78, sumA[7], sumA[8]);
        unpack2(dB, lo, hi);  sumB[0] = lo + hi;
        unpack2(B12, sumB[1], sumB[2]); unpack2(B34, sumB[3], sumB[4]);
        unpack2(B56, sumB[5], sumB[6]); unpack2(B78, sumB[7], sumB[8]);
    } else {
        #pragma unroll
        for (int c = 0; c < CREP; c++) { sumA[c] = 0.0f; sumB[c] = 0.0f; }
        for (int n = n0; n < n0 + NCHUNK; n++) {
            float xv = s_x[n];
            const float4 ya = *(const float4*)&s_y[n * CIN];
            const float4 yb = *(const float4*)&s_y[n * CIN + 4];
            float aA = xv - tmA, dAa = aA * aA;
            float aB = xv - tmB, dBb = aB * aB;
            sumA[0] += ex2(dAa * kk[0]);
            sumA[1] = fmaf(ex2(dAa * kk[1]), ya.x, sumA[1]);
            sumA[2] = fmaf(ex2(dAa * kk[2]), ya.y, sumA[2]);
            sumA[3] = fmaf(ex2(dAa * kk[3]), ya.z, sumA[3]);
            sumA[4] = fmaf(ex2(dAa * kk[4]), ya.w, sumA[4]);
            sumA[5] = fmaf(ex2(dAa * kk[5]), yb.x, sumA[5]);
            sumA[6] = fmaf(ex2(dAa * kk[6]), yb.y, sumA[6]);
            sumA[7] = fmaf(ex2(dAa * kk[7]), yb.z, sumA[7]);
            sumA[8] = fmaf(ex2(dAa * kk[8]), yb.w, sumA[8]);
            sumB[0] += ex2(dBb * kk[0]);
            sumB[1] = fmaf(ex2(dBb * kk[1]), ya.x, sumB[1]);
            sumB[2] = fmaf(ex2(dBb * kk[2]), ya.y, sumB[2]);
            sumB[3] = fmaf(ex2(dBb * kk[3]), ya.z, sumB[3]);
            sumB[4] = fmaf(ex2(dBb * kk[4]), ya.w, sumB[4]);
            sumB[5] = fmaf(ex2(dBb * kk[5]), yb.x, sumB[5]);
            sumB[6] = fmaf(ex2(dBb * kk[6]), yb.y, sumB[6]);
            sumB[7] = fmaf(ex2(dBb * kk[7]), yb.z, sumB[7]);
            sumB[8] = fmaf(ex2(dBb * kk[8]), yb.w, sumB[8]);
        }
    }

    // Block-local reduce over the 8 warps, then one partial row to global scratch.
    __syncthreads();                       // s_y no longer needed
    float* red = s_pool;                   // [WARPS][MBLK][CREP]
    #pragma unroll
    for (int c = 0; c < CREP; c++) {
        red[(ns * MBLK + lane)      * CREP + c] = sumA[c];
        red[(ns * MBLK + lane + 32) * CREP + c] = sumB[c];
    }
    __syncthreads();

    const int base = ((nb * B_ + b) * MVAL + mt * MBLK) * CREP;
    for (int i = tid; i < MBLK * CREP; i += NTHREADS) {
        float s = 0.0f;
        #pragma unroll
        for (int w = 0; w < WARPS; w++)
            s += red[w * (MBLK * CREP) + i];
        g_part[base + i] = s;
    }
}

__global__ __launch_bounds__(256)
void convcnp_finish(const float* __restrict__ gW,
                    const float* __restrict__ gbias,
                    float* __restrict__ gout)
{
    const int gm = blockIdx.x * 256 + threadIdx.x;   // [0, B*M)
    const int b  = gm >> 10;
    const int m  = gm & (MVAL - 1);

    float tot[CREP];
    #pragma unroll
    for (int c = 0; c < CREP; c++) tot[c] = 0.0f;
    #pragma unroll
    for (int nb = 0; nb < NSG; nb++) {
        const float* p = &g_part[((nb * B_ + b) * MVAL + m) * CREP];
        #pragma unroll
        for (int c = 0; c < CREP; c++) tot[c] += p[c];
    }

    float density = tot[0];
    float inv = 1.0f / (density + 1e-8f);
    float yv[CREP];
    yv[0] = density;
    #pragma unroll
    for (int c = 1; c < CREP; c++) yv[c] = tot[c] * inv;

    float4 o4[COUT / 4];
    #pragma unroll
    for (int o = 0; o < COUT; o++) {
        float r = __ldg(&gbias[o]);
        #pragma unroll
        for (int c = 0; c < CREP; c++)
            r = fmaf(__ldg(&gW[o * CREP + c]), yv[c], r);
        ((float*)o4)[o] = r;
    }
    float4* orow = (float4*)(gout + (size_t)gm * COUT);
    #pragma unroll
    for (int q = 0; q < COUT / 4; q++) orow[q] = o4[q];
}

extern "C" void kernel_launch(void* const* d_in, const int* in_sizes, int n_in,
                              void* d_out, int out_size) {
    const float* x     = (const float*)d_in[0];
    const float* y     = (const float*)d_in[1];
    const float* t     = (const float*)d_in[2];
    const float* sigma = (const float*)d_in[3];
    const float* W     = (const float*)d_in[4];
    const float* bias  = (const float*)d_in[5];
    float* out = (float*)d_out;

    convcnp_partial<<<B_ * 16 * NSG, NTHREADS>>>(x, y, t, sigma);   // 1024 blocks
    convcnp_finish<<<(B_ * MVAL) / 256, 256>>>(W, bias, out);       // 32 blocks
}

// round 5
// speedup vs baseline: 1.1552x; 1.1552x over previous
#include <cuda_runtime.h>
#include <cuda_bf16.h>

#define B_      8
#define NVAL    1024
#define MVAL    1024
#define CIN     8
#define CREP    9
#define COUT    16

#define NSG     4                    // n-splits across blocks
#define NBLKN   (NVAL / NSG)         // 256 n per block
#define MBLK    64                   // m per block (2 per lane)
#define WARPS   8                    // warps per block
#define NTHREADS (32 * WARPS)        // 256
#define NCHUNK  (NBLKN / WARPS)      // 32 n per warp

typedef unsigned long long u64;

// Partial sums: [NSG][B][M][CREP] = 1.18MB (stays L2-resident)
__device__ float g_part[NSG * B_ * MVAL * CREP];

__device__ __forceinline__ u64 pack2(float lo, float hi) {
    u64 r; asm("mov.b64 %0, {%1, %2};" : "=l"(r) : "f"(lo), "f"(hi)); return r;
}
__device__ __forceinline__ void unpack2(u64 v, float& lo, float& hi) {
    asm("mov.b64 {%0, %1}, %2;" : "=f"(lo), "=f"(hi) : "l"(v));
}
__device__ __forceinline__ u64 add2(u64 a, u64 b) {
    u64 r; asm("add.rn.f32x2 %0, %1, %2;" : "=l"(r) : "l"(a), "l"(b)); return r;
}
__device__ __forceinline__ u64 mul2(u64 a, u64 b) {
    u64 r; asm("mul.rn.f32x2 %0, %1, %2;" : "=l"(r) : "l"(a), "l"(b)); return r;
}
__device__ __forceinline__ u64 fma2(u64 a, u64 b, u64 c) {
    u64 r; asm("fma.rn.f32x2 %0, %1, %2, %3;" : "=l"(r) : "l"(a), "l"(b), "l"(c)); return r;
}
__device__ __forceinline__ float ex2(float x) {   // MUFU.EX2
    float r; asm("ex2.approx.f32 %0, %1;" : "=f"(r) : "f"(x)); return r;
}

__global__ __launch_bounds__(NTHREADS)
void convcnp_partial(const float* __restrict__ gx,
                     const float* __restrict__ gy,
                     const float* __restrict__ gt,
                     const float* __restrict__ gsigma)
{
    __shared__ float s_x [NBLKN];
    __shared__ float s_xn[NBLKN];
    __shared__ float s_pool[WARPS * MBLK * CREP];   // 4608 floats; first 2048 double as s_y

    float* s_y = s_pool;

    const int nb   = blockIdx.x & (NSG - 1);
    const int mt   = (blockIdx.x >> 2) & 15;
    const int b    = blockIdx.x >> 6;
    const int tid  = threadIdx.x;
    const int lane = tid & 31;
    const int ns   = tid >> 5;

    float kk[CREP];
    bool same = true;
    #pragma unroll
    for (int c = 0; c < CREP; c++) {
        float s = __expf(gsigma[c]);
        kk[c] = -0.5f * 1.4426950408889634f / (s * s);
        if (c > 0 && kk[c] != kk[0]) same = false;
    }
    const float sf = same ? sqrtf(-kk[0]) : 1.0f;

    const int nbase = nb * NBLKN;

    for (int i = tid; i < NBLKN; i += NTHREADS) {
        float v = gx[b * NVAL + nbase + i] * sf;
        s_x [i] =  v;
        s_xn[i] = -v;
    }
    {
        const float4* y4 = (const float4*)(gy + (b * NVAL + nbase) * CIN);
        float4* sy4 = (float4*)s_y;
        #pragma unroll
        for (int i = tid; i < NBLKN * CIN / 4; i += NTHREADS)
            sy4[i] = y4[i];
    }
    const int   m0  = mt * MBLK + lane;
    const int   m1  = m0 + 32;
    const float tmA = gt[b * MVAL + m0] * sf;
    const float tmB = gt[b * MVAL + m1] * sf;
    __syncthreads();

    const int n0 = ns * NCHUNK;
    float sumA[CREP], sumB[CREP];

    if (same) {
        const u64 ttA  = pack2( tmA,  tmA), nttA = pack2(-tmA, -tmA);
        const u64 ttB  = pack2( tmB,  tmB), nttB = pack2(-tmB, -tmB);
        u64 dA = 0, A12 = 0, A34 = 0, A56 = 0, A78 = 0;
        u64 dB = 0, B12 = 0, B34 = 0, B56 = 0, B78 = 0;

        #pragma unroll 4
        for (int n = n0; n < n0 + NCHUNK; n += 2) {
            u64 x2  = *(const u64*)&s_x [n];
            u64 xn2 = *(const u64*)&s_xn[n];
            ulonglong2 yA = *(const ulonglong2*)&s_y[n * CIN];
            ulonglong2 yB = *(const ulonglong2*)&s_y[n * CIN + 4];
            ulonglong2 zA = *(const ulonglong2*)&s_y[(n + 1) * CIN];
            ulonglong2 zB = *(const ulonglong2*)&s_y[(n + 1) * CIN + 4];

            u64 dd = mul2(add2(x2, nttA), add2(xn2, ttA));   // -(x-t)^2, pre-scaled
            float d0, d1; unpack2(dd, d0, d1);
            float e0 = ex2(d0), e1 = ex2(d1);
            dA = add2(dA, pack2(e0, e1));
            u64 e00 = pack2(e0, e0), e11 = pack2(e1, e1);
            A12 = fma2(e00, yA.x, A12);  A34 = fma2(e00, yA.y, A34);
            A56 = fma2(e00, yB.x, A56);  A78 = fma2(e00, yB.y, A78);
            A12 = fma2(e11, zA.x, A12);  A34 = fma2(e11, zA.y, A34);
            A56 = fma2(e11, zB.x, A56);  A78 = fma2(e11, zB.y, A78);

            u64 gg = mul2(add2(x2, nttB), add2(xn2, ttB));
            float g0, g1; unpack2(gg, g0, g1);
            float f0 = ex2(g0), f1 = ex2(g1);
            dB = add2(dB, pack2(f0, f1));
            u64 f00 = pack2(f0, f0), f11 = pack2(f1, f1);
            B12 = fma2(f00, yA.x, B12);  B34 = fma2(f00, yA.y, B34);
            B56 = fma2(f00, yB.x, B56);  B78 = fma2(f00, yB.y, B78);
            B12 = fma2(f11, zA.x, B12);  B34 = fma2(f11, zA.y, B34);
            B56 = fma2(f11, zB.x, B56);  B78 = fma2(f11, zB.y, B78);
        }
        float lo, hi;
        unpack2(dA, lo, hi);  sumA[0] = lo + hi;
        unpack2(A12, sumA[1], sumA[2]); unpack2(A34, sumA[3], sumA[4]);
        unpack2(A56, sumA[5], sumA[6]); unpack2(A78, sumA[7], sumA[8]);
        unpack2(dB, lo, hi);  sumB[0] = lo + hi;
        unpack2(B12, sumB[1], sumB[2]); unpack2(B34, sumB[3], sumB[4]);
        unpack2(B56, sumB[5], sumB[6]); unpack2(B78, sumB[7], sumB[8]);
    } else {
        #pragma unroll
        for (int c = 0; c < CREP; c++) { sumA[c] = 0.0f; sumB[c] = 0.0f; }
        for (int n = n0; n < n0 + NCHUNK; n++) {
            float xv = s_x[n];
            const float4 ya = *(const float4*)&s_y[n * CIN];
            const float4 yb = *(const float4*)&s_y[n * CIN + 4];
            float aA = xv - tmA, dAa = aA * aA;
            float aB = xv - tmB, dBb = aB * aB;
            sumA[0] += ex2(dAa * kk[0]);
            sumA[1] = fmaf(ex2(dAa * kk[1]), ya.x, sumA[1]);
            sumA[2] = fmaf(ex2(dAa * kk[2]), ya.y, sumA[2]);
            sumA[3] = fmaf(ex2(dAa * kk[3]), ya.z, sumA[3]);
            sumA[4] = fmaf(ex2(dAa * kk[4]), ya.w, sumA[4]);
            sumA[5] = fmaf(ex2(dAa * kk[5]), yb.x, sumA[5]);
            sumA[6] = fmaf(ex2(dAa * kk[6]), yb.y, sumA[6]);
            sumA[7] = fmaf(ex2(dAa * kk[7]), yb.z, sumA[7]);
            sumA[8] = fmaf(ex2(dAa * kk[8]), yb.w, sumA[8]);
            sumB[0] += ex2(dBb * kk[0]);
            sumB[1] = fmaf(ex2(dBb * kk[1]), ya.x, sumB[1]);
            sumB[2] = fmaf(ex2(dBb * kk[2]), ya.y, sumB[2]);
            sumB[3] = fmaf(ex2(dBb * kk[3]), ya.z, sumB[3]);
            sumB[4] = fmaf(ex2(dBb * kk[4]), ya.w, sumB[4]);
            sumB[5] = fmaf(ex2(dBb * kk[5]), yb.x, sumB[5]);
            sumB[6] = fmaf(ex2(dBb * kk[6]), yb.y, sumB[6]);
            sumB[7] = fmaf(ex2(dBb * kk[7]), yb.z, sumB[7]);
            sumB[8] = fmaf(ex2(dBb * kk[8]), yb.w, sumB[8]);
        }
    }

    // Block-local reduce over the 8 warps, then one partial row to global scratch.
    __syncthreads();                       // s_y no longer needed
    float* red = s_pool;                   // [WARPS][MBLK][CREP]
    #pragma unroll
    for (int c = 0; c < CREP; c++) {
        red[(ns * MBLK + lane)      * CREP + c] = sumA[c];
        red[(ns * MBLK + lane + 32) * CREP + c] = sumB[c];
    }
    __syncthreads();

    const int base = ((nb * B_ + b) * MVAL + mt * MBLK) * CREP;
    for (int i = tid; i < MBLK * CREP; i += NTHREADS) {
        float s = 0.0f;
        #pragma unroll
        for (int w = 0; w < WARPS; w++)
            s += red[w * (MBLK * CREP) + i];
        g_part[base + i] = s;
    }
}

// 256 blocks x 288 threads. Block = 32 m of one batch.
// Thread t < 288 sums the 4 nb-partials at contiguous offset t (coalesced),
// then 32 threads do the 9->16 GEMV.
#define FTHREADS 288
#define FM       32
__global__ __launch_bounds__(FTHREADS)
void convcnp_finish(const float* __restrict__ gW,
                    const float* __restrict__ gbias,
                    float* __restrict__ gout)
{
    __shared__ float s_tot[FM * CREP];   // 288

    const int b   = blockIdx.x >> 5;          // 32 m-tiles per batch
    const int mt  = blockIdx.x & 31;
    const int m0  = mt * FM;
    const int t   = threadIdx.x;

    if (t < FM * CREP) {
        const int off = (b * MVAL + m0) * CREP + t;
        float s = 0.0f;
        #pragma unroll
        for (int nb = 0; nb < NSG; nb++)
            s += g_part[nb * (B_ * MVAL * CREP) + off];
        s_tot[t] = s;
    }
    __syncthreads();

    if (t < FM) {
        float yv[CREP];
        float density = s_tot[t * CREP];
        float inv = 1.0f / (density + 1e-8f);
        yv[0] = density;
        #pragma unroll
        for (int c = 1; c < CREP; c++) yv[c] = s_tot[t * CREP + c] * inv;

        float4 o4[COUT / 4];
        #pragma unroll
        for (int o = 0; o < COUT; o++) {
            float r = __ldg(&gbias[o]);
            #pragma unroll
            for (int c = 0; c < CREP; c++)
                r = fmaf(__ldg(&gW[o * CREP + c]), yv[c], r);
            ((float*)o4)[o] = r;
        }
        float4* orow = (float4*)(gout + ((size_t)b * MVAL + m0 + t) * COUT);
        #pragma unroll
        for (int q = 0; q < COUT / 4; q++) orow[q] = o4[q];
    }
}

extern "C" void kernel_launch(void* const* d_in, const int* in_sizes, int n_in,
                              void* d_out, int out_size) {
    const float* x     = (const float*)d_in[0];
    const float* y     = (const float*)d_in[1];
    const float* t     = (const float*)d_in[2];
    const float* sigma = (const float*)d_in[3];
    const float* W     = (const float*)d_in[4];
    const float* bias  = (const float*)d_in[5];
    float* out = (float*)d_out;

    convcnp_partial<<<B_ * 16 * NSG, NTHREADS>>>(x, y, t, sigma);   // 512 blocks
    convcnp_finish<<<B_ * 32, FTHREADS>>>(W, bias, out);            // 256 blocks
}